// round 1
// baseline (speedup 1.0000x reference)
#include <cuda_runtime.h>
#include <cuda_bf16.h>
#include <cstddef>

// Problem constants (fixed by the dataset)
#define BATCH 64
#define LSEQ  512
#define DIN   256
#define HDIM  256
#define H3    768
#define ADIM  128
#define DEPTH 4
#define NROWS (LSEQ * BATCH)   // 32768

// ---------------- scratch (device globals; no allocation allowed) -------------
__device__ float g_hseq[(size_t)NROWS * HDIM];      // (L,B,H)   32MB
__device__ float g_xp  [(size_t)NROWS * H3];        // (L,B,3H)  96MB
__device__ float g_xa  [(size_t)NROWS * ADIM];      // (L,B,A)   16MB
__device__ float g_Ut2 [(size_t)(H3 + ADIM) * HDIM];// [U^T ; Ua1^T] 896x256
__device__ unsigned char g_mask[BATCH * LSEQ];

// ---------------------------------- helpers ----------------------------------
__device__ __forceinline__ float warp_sum(float v) {
#pragma unroll
    for (int o = 16; o > 0; o >>= 1) v += __shfl_down_sync(0xffffffffu, v, o);
    return v;
}
__device__ __forceinline__ float dp4(float4 a, float4 b) {
    return a.x * b.x + a.y * b.y + a.z * b.z + a.w * b.w;
}
__device__ __forceinline__ float sigmoidf(float x) { return 1.0f / (1.0f + expf(-x)); }

// ------------------------- prep: weight transpose ----------------------------
// g_Ut2 row k (k<768)  = U[:,k]   (U is (256,768) row-major)
// g_Ut2 row 768+k      = Ua1[:,k] (Ua1 is (256,128))
__global__ void prep_weights(const float* __restrict__ U, const float* __restrict__ Ua1) {
    int k = blockIdx.x;          // 0..895
    int i = threadIdx.x;         // 0..255
    float v = (k < H3) ? U[(size_t)i * H3 + k] : Ua1[(size_t)i * ADIM + (k - H3)];
    g_Ut2[(size_t)k * HDIM + i] = v;
}

// ------------------- mask copy with dtype auto-detection ---------------------
// bool(np.bool_)=1 byte vs int32=4 bytes. Row b=0 has length>=256 so bytes at
// offsets 1..255 are 1 if u8; if int32, bytes at (4i+1..3) are always 0.
__global__ void copy_mask(const unsigned char* __restrict__ m8) {
    __shared__ int mode;
    if (threadIdx.x == 0) {
        int nz = 0;
        for (int i = 0; i < 64; i++) nz |= m8[4 * i + 1] | m8[4 * i + 2] | m8[4 * i + 3];
        mode = nz ? 1 : 0;
    }
    __syncthreads();
    if (mode) {
        for (int i = threadIdx.x; i < BATCH * LSEQ; i += blockDim.x)
            g_mask[i] = m8[i] ? 1 : 0;
    } else {
        const int* m32 = (const int*)m8;
        for (int i = threadIdx.x; i < BATCH * LSEQ; i += blockDim.x)
            g_mask[i] = m32[i] ? 1 : 0;
    }
}

// ------------------------------- tiled SGEMM ---------------------------------
// C(MxN) = A(MxK) @ B(KxN) [+ bias], K=256 fixed, M%64==0, N%64==0... N in {128,256,768}.
// REMAP: A row r corresponds to x[b=r%64][l=r/64][:]  (x is (B,L,DIN))
template <bool REMAP>
__global__ void __launch_bounds__(256) sgemm_kernel(
    const float* __restrict__ A, const float* __restrict__ Bm,
    const float* __restrict__ bias, float* __restrict__ C, int N) {
    const int K = 256;
    __shared__ __align__(16) float Ast[16][68];   // [kk][row]
    __shared__ __align__(16) float Bs[16][64];
    int t  = threadIdx.x;
    int m0 = blockIdx.y * 64;
    int n0 = blockIdx.x * 64;
    int ty = t >> 4, tx = t & 15;

    float acc[4][4];
#pragma unroll
    for (int i = 0; i < 4; i++)
#pragma unroll
        for (int j = 0; j < 4; j++) acc[i][j] = 0.0f;

    int ar = t >> 2;             // 0..63
    int ak = (t & 3) * 4;        // 0,4,8,12
    int arow = m0 + ar;
    const float* Aptr;
    if (REMAP) {
        int b = arow & 63, l = arow >> 6;
        Aptr = A + ((size_t)b * LSEQ + l) * K;
    } else {
        Aptr = A + (size_t)arow * K;
    }
    int bk = t >> 4;             // 0..15
    int bn = (t & 15) * 4;       // 0..60

    for (int k0 = 0; k0 < K; k0 += 16) {
        float4 av = *(const float4*)(Aptr + k0 + ak);
        Ast[ak + 0][ar] = av.x;
        Ast[ak + 1][ar] = av.y;
        Ast[ak + 2][ar] = av.z;
        Ast[ak + 3][ar] = av.w;
        *(float4*)(&Bs[bk][bn]) = *(const float4*)(Bm + (size_t)(k0 + bk) * N + n0 + bn);
        __syncthreads();
#pragma unroll
        for (int kk = 0; kk < 16; kk++) {
            float4 a  = *(const float4*)(&Ast[kk][ty * 4]);
            float4 bb = *(const float4*)(&Bs[kk][tx * 4]);
            acc[0][0] += a.x * bb.x; acc[0][1] += a.x * bb.y; acc[0][2] += a.x * bb.z; acc[0][3] += a.x * bb.w;
            acc[1][0] += a.y * bb.x; acc[1][1] += a.y * bb.y; acc[1][2] += a.y * bb.z; acc[1][3] += a.y * bb.w;
            acc[2][0] += a.z * bb.x; acc[2][1] += a.z * bb.y; acc[2][2] += a.z * bb.z; acc[2][3] += a.z * bb.w;
            acc[3][0] += a.w * bb.x; acc[3][1] += a.w * bb.y; acc[3][2] += a.w * bb.z; acc[3][3] += a.w * bb.w;
        }
        __syncthreads();
    }
#pragma unroll
    for (int i = 0; i < 4; i++) {
        int row = m0 + ty * 4 + i;
        float4 v;
        v.x = acc[i][0]; v.y = acc[i][1]; v.z = acc[i][2]; v.w = acc[i][3];
        if (bias) {
            v.x += bias[n0 + tx * 4 + 0];
            v.y += bias[n0 + tx * 4 + 1];
            v.z += bias[n0 + tx * 4 + 2];
            v.w += bias[n0 + tx * 4 + 3];
        }
        *(float4*)(&C[(size_t)row * N + n0 + tx * 4]) = v;
    }
}

// ------------------------- rowwise LayerNorm over 768 ------------------------
__global__ void __launch_bounds__(256) ln_rows(float* __restrict__ xp,
                                               const float* __restrict__ gammas,
                                               const float* __restrict__ betas) {
    int r = blockIdx.x;
    float* row = xp + (size_t)r * H3;
    int t = threadIdx.x;  // 256
    float v0 = row[t], v1 = row[t + 256], v2 = row[t + 512];
    float s = v0 + v1 + v2;
    float q = v0 * v0 + v1 * v1 + v2 * v2;
    __shared__ float rs[8], rq[8];
    __shared__ float s_mu, s_rstd;
    float ws = warp_sum(s), wq = warp_sum(q);
    if ((t & 31) == 0) { rs[t >> 5] = ws; rq[t >> 5] = wq; }
    __syncthreads();
    if (t == 0) {
        float S = 0.f, Q = 0.f;
#pragma unroll
        for (int i = 0; i < 8; i++) { S += rs[i]; Q += rq[i]; }
        float mu  = S * (1.0f / 768.0f);
        float var = Q * (1.0f / 768.0f) - mu * mu;
        s_mu = mu;
        s_rstd = rsqrtf(var + 1e-5f);
    }
    __syncthreads();
    float mu = s_mu, rstd = s_rstd;
    row[t]       = gammas[t]       * (v0 - mu) * rstd + betas[t];
    row[t + 256] = gammas[t + 256] * (v1 - mu) * rstd + betas[t + 256];
    row[t + 512] = gammas[t + 512] * (v2 - mu) * rstd + betas[t + 512];
}

// ------------------------------ sequential scan -------------------------------
// One CTA per batch element, 896 threads: t<768 compute hp cols, t>=768 compute
// the 128 action-head dots. Loops 512 timesteps internally (no inter-CTA deps).
__global__ void __launch_bounds__(896) scan_kernel(
    int d,
    const float* __restrict__ bg,      // b (768)
    const float* __restrict__ gammas,  // (2,768)
    const float* __restrict__ betas,   // (2,768)
    const float* __restrict__ ba1,     // (128)
    const float* __restrict__ Wa2,     // (128,2)
    const float* __restrict__ ba2,     // (2)
    float* __restrict__ out, int out_size) {
    int b = blockIdx.x;
    int t = threadIdx.x;

    __shared__ float sh[HDIM];          // h carry
    __shared__ float shp[H3];           // hp (raw then normalized)
    __shared__ float sa[ADIM];          // h @ Ua1
    __shared__ float shnew[HDIM];
    __shared__ float rsum[28], rq2[28], rl0[4], rl1[4];
    __shared__ float s_mu, s_rs;
    __shared__ float c_g1[H3], c_b1[H3], c_bg[H3], c_ba1[ADIM], c_wa2[2 * ADIM];

    for (int i = t; i < H3; i += 896) {
        c_g1[i] = gammas[H3 + i];
        c_b1[i] = betas[H3 + i];
        c_bg[i] = bg[i];
    }
    if (t < ADIM) c_ba1[t] = ba1[t];
    if (t < 2 * ADIM) c_wa2[t] = Wa2[t];
    if (t < HDIM) sh[t] = 0.0f;
    __syncthreads();

    const bool write_full = (out_size >= 409600);
    const float4* up = ((const float4*)g_Ut2) + (size_t)t * 64;

    for (int l = 0; l < LSEQ; ++l) {
        // ---- phase 1: matvec h @ [U | Ua1] ----
        const float4* h4 = (const float4*)sh;
        float a0 = 0.f, a1 = 0.f, a2 = 0.f, a3 = 0.f;
#pragma unroll 8
        for (int i = 0; i < 64; i += 4) {
            a0 += dp4(up[i], h4[i]);
            a1 += dp4(up[i + 1], h4[i + 1]);
            a2 += dp4(up[i + 2], h4[i + 2]);
            a3 += dp4(up[i + 3], h4[i + 3]);
        }
        float dot = (a0 + a1) + (a2 + a3);
        if (t < H3) shp[t] = dot; else sa[t - H3] = dot;

        // ---- phase 2: LN stats over 768 ----
        float v  = (t < H3) ? dot : 0.0f;
        float ws = warp_sum(v);
        float wq = warp_sum(v * v);
        if ((t & 31) == 0) { rsum[t >> 5] = ws; rq2[t >> 5] = wq; }
        __syncthreads();
        if (t == 0) {
            float S = 0.f, Q = 0.f;
#pragma unroll
            for (int i = 0; i < 28; i++) { S += rsum[i]; Q += rq2[i]; }
            float mu  = S * (1.0f / 768.0f);
            float var = Q * (1.0f / 768.0f) - mu * mu;
            s_mu = mu;
            s_rs = rsqrtf(var + 1e-5f);
        }
        __syncthreads();
        if (t < H3) shp[t] = c_g1[t] * (shp[t] - s_mu) * s_rs + c_b1[t];
        __syncthreads();

        // ---- phase 3: gates (t<256) + action head (t>=768) ----
        unsigned char mt = g_mask[b * LSEQ + l];
        size_t rowbase = (size_t)l * BATCH + b;
        if (t < HDIM) {
            const float* xpr = g_xp + rowbase * H3;
            float r  = sigmoidf(xpr[t]         + shp[t]         + c_bg[t]);
            float z  = sigmoidf(xpr[256 + t]   + shp[256 + t]   + c_bg[256 + t]);
            float hh = tanhf   (xpr[512 + t]   + r * shp[512 + t] + c_bg[512 + t]);
            float hn = z * sh[t] + (1.0f - z) * hh;
            float ho = mt ? hn : sh[t];
            shnew[t] = ho;
            g_hseq[rowbase * HDIM + t] = ho;
            if (d == DEPTH - 1 && l == LSEQ - 1 && out_size >= BATCH * HDIM)
                out[b * HDIM + t] = ho;
        } else if (t >= H3) {
            int k = t - H3;
            float tv = tanhf(g_xa[rowbase * ADIM + k] + sa[k] + c_ba1[k]);
            float p0 = warp_sum(tv * c_wa2[2 * k]);
            float p1 = warp_sum(tv * c_wa2[2 * k + 1]);
            if ((t & 31) == 0) { rl0[k >> 5] = p0; rl1[k >> 5] = p1; }
        }
        __syncthreads();

        // ---- phase 4: softmax / action / mask update ----
        if (t == 0) {
            float l0 = rl0[0] + rl0[1] + rl0[2] + rl0[3] + ba2[0];
            float l1 = rl1[0] + rl1[1] + rl1[2] + rl1[3] + ba2[1];
            bool act = (l1 > l0) && mt;
            float m = fmaxf(l0, l1);
            float e0 = expf(l0 - m), e1 = expf(l1 - m);
            float inv = 1.0f / (e0 + e1);
            if (write_full) {
                size_t ai = (size_t)BATCH * HDIM + ((size_t)(b * DEPTH + d)) * LSEQ + l;
                out[ai] = act ? 1.0f : 0.0f;
                size_t pi = (size_t)BATCH * HDIM + (size_t)BATCH * DEPTH * LSEQ +
                            (((size_t)(b * DEPTH + d)) * LSEQ + l) * 2;
                out[pi]     = e0 * inv;
                out[pi + 1] = e1 * inv;
            }
            g_mask[b * LSEQ + l] = act ? 1 : 0;  // next-depth mask = m & act
        }
        if (t < HDIM) sh[t] = shnew[t];
        __syncthreads();
    }
}

// --------------------------------- launcher ----------------------------------
extern "C" void kernel_launch(void* const* d_in, const int* in_sizes, int n_in,
                              void* d_out, int out_size) {
    const float* x     = (const float*)d_in[0];
    const unsigned char* mask = (const unsigned char*)d_in[1];
    const float* W_emb = (const float*)d_in[2];
    const float* b_emb = (const float*)d_in[3];
    const float* W     = (const float*)d_in[4];
    const float* U     = (const float*)d_in[5];
    const float* bgate = (const float*)d_in[6];
    const float* Wa1   = (const float*)d_in[7];
    const float* Ua1   = (const float*)d_in[8];
    const float* ba1   = (const float*)d_in[9];
    const float* Wa2   = (const float*)d_in[10];
    const float* ba2   = (const float*)d_in[11];
    const float* gammas = (const float*)d_in[12];
    const float* betas  = (const float*)d_in[13];
    float* out = (float*)d_out;

    float *hseq, *xp, *xa;
    cudaGetSymbolAddress((void**)&hseq, g_hseq);
    cudaGetSymbolAddress((void**)&xp, g_xp);
    cudaGetSymbolAddress((void**)&xa, g_xa);

    prep_weights<<<H3 + ADIM, HDIM>>>(U, Ua1);
    copy_mask<<<1, 1024>>>(mask);

    // embed: h_seq(l*64+b,:) = x[b,l,:] @ W_emb + b_emb
    sgemm_kernel<true><<<dim3(HDIM / 64, NROWS / 64), 256>>>(x, W_emb, b_emb, hseq, HDIM);

    for (int d = 0; d < DEPTH; d++) {
        sgemm_kernel<false><<<dim3(H3 / 64, NROWS / 64), 256>>>(hseq, W, nullptr, xp, H3);
        sgemm_kernel<false><<<dim3(ADIM / 64, NROWS / 64), 256>>>(hseq, Wa1, nullptr, xa, ADIM);
        ln_rows<<<NROWS, 256>>>(xp, gammas, betas);
        scan_kernel<<<BATCH, 896>>>(d, bgate, gammas, betas, ba1, Wa2, ba2, out, out_size);
    }
}

// round 2
// speedup vs baseline: 2.9738x; 2.9738x over previous
#include <cuda_runtime.h>
#include <cuda_bf16.h>
#include <cstddef>

// Problem constants (fixed by the dataset)
#define BATCH 64
#define LSEQ  512
#define DIN   256
#define HDIM  256
#define H3    768
#define ADIM  128
#define DEPTH 4
#define NROWS (LSEQ * BATCH)   // 32768

#define CLUSTER_NCTAS 8
#define ROWS_PER_CTA  112      // 896 / 8
#define NBAT          4        // batches per cluster
#define NCLU          16       // 64 / 4
#define W_PAD         260      // 256 + 4 pad for bank-conflict-free LDS.128
#define SCAN_THREADS  896

// ---------------- scratch (device globals; no allocation allowed) -------------
__device__ float g_hseq[(size_t)NROWS * HDIM];      // (L,B,H)
__device__ float g_xp  [(size_t)NROWS * H3];        // (L,B,3H)
__device__ float g_xa  [(size_t)NROWS * ADIM];      // (L,B,A)
__device__ float g_Ut2 [(size_t)(H3 + ADIM) * HDIM];// [U^T ; Ua1^T] 896x256
__device__ float g_hp  [(size_t)NCLU * 2 * 896 * NBAT]; // matvec exchange (double buffered)
__device__ unsigned char g_mask[BATCH * LSEQ];

// ---------------------------------- helpers ----------------------------------
__device__ __forceinline__ float warp_sum(float v) {
#pragma unroll
    for (int o = 16; o > 0; o >>= 1) v += __shfl_down_sync(0xffffffffu, v, o);
    return v;
}
__device__ __forceinline__ float dp4(float4 a, float4 b) {
    return a.x * b.x + a.y * b.y + a.z * b.z + a.w * b.w;
}
__device__ __forceinline__ float sigmoidf(float x) { return 1.0f / (1.0f + expf(-x)); }

// ------------------------- prep: weight transpose ----------------------------
__global__ void prep_weights(const float* __restrict__ U, const float* __restrict__ Ua1) {
    int k = blockIdx.x;          // 0..895
    int i = threadIdx.x;         // 0..255
    float v = (k < H3) ? U[(size_t)i * H3 + k] : Ua1[(size_t)i * ADIM + (k - H3)];
    g_Ut2[(size_t)k * HDIM + i] = v;
}

// ------------------- mask copy with dtype auto-detection ---------------------
__global__ void copy_mask(const unsigned char* __restrict__ m8) {
    __shared__ int mode;
    if (threadIdx.x == 0) {
        int nz = 0;
        for (int i = 0; i < 64; i++) nz |= m8[4 * i + 1] | m8[4 * i + 2] | m8[4 * i + 3];
        mode = nz ? 1 : 0;
    }
    __syncthreads();
    if (mode) {
        for (int i = threadIdx.x; i < BATCH * LSEQ; i += blockDim.x)
            g_mask[i] = m8[i] ? 1 : 0;
    } else {
        const int* m32 = (const int*)m8;
        for (int i = threadIdx.x; i < BATCH * LSEQ; i += blockDim.x)
            g_mask[i] = m32[i] ? 1 : 0;
    }
}

// ------------------------------- tiled SGEMM ---------------------------------
template <bool REMAP>
__global__ void __launch_bounds__(256) sgemm_kernel(
    const float* __restrict__ A, const float* __restrict__ Bm,
    const float* __restrict__ bias, float* __restrict__ C, int N) {
    const int K = 256;
    __shared__ __align__(16) float Ast[16][68];   // [kk][row]
    __shared__ __align__(16) float Bs[16][64];
    int t  = threadIdx.x;
    int m0 = blockIdx.y * 64;
    int n0 = blockIdx.x * 64;
    int ty = t >> 4, tx = t & 15;

    float acc[4][4];
#pragma unroll
    for (int i = 0; i < 4; i++)
#pragma unroll
        for (int j = 0; j < 4; j++) acc[i][j] = 0.0f;

    int ar = t >> 2;
    int ak = (t & 3) * 4;
    int arow = m0 + ar;
    const float* Aptr;
    if (REMAP) {
        int b = arow & 63, l = arow >> 6;
        Aptr = A + ((size_t)b * LSEQ + l) * K;
    } else {
        Aptr = A + (size_t)arow * K;
    }
    int bk = t >> 4;
    int bn = (t & 15) * 4;

    for (int k0 = 0; k0 < K; k0 += 16) {
        float4 av = *(const float4*)(Aptr + k0 + ak);
        Ast[ak + 0][ar] = av.x;
        Ast[ak + 1][ar] = av.y;
        Ast[ak + 2][ar] = av.z;
        Ast[ak + 3][ar] = av.w;
        *(float4*)(&Bs[bk][bn]) = *(const float4*)(Bm + (size_t)(k0 + bk) * N + n0 + bn);
        __syncthreads();
#pragma unroll
        for (int kk = 0; kk < 16; kk++) {
            float4 a  = *(const float4*)(&Ast[kk][ty * 4]);
            float4 bb = *(const float4*)(&Bs[kk][tx * 4]);
            acc[0][0] += a.x * bb.x; acc[0][1] += a.x * bb.y; acc[0][2] += a.x * bb.z; acc[0][3] += a.x * bb.w;
            acc[1][0] += a.y * bb.x; acc[1][1] += a.y * bb.y; acc[1][2] += a.y * bb.z; acc[1][3] += a.y * bb.w;
            acc[2][0] += a.z * bb.x; acc[2][1] += a.z * bb.y; acc[2][2] += a.z * bb.z; acc[2][3] += a.z * bb.w;
            acc[3][0] += a.w * bb.x; acc[3][1] += a.w * bb.y; acc[3][2] += a.w * bb.z; acc[3][3] += a.w * bb.w;
        }
        __syncthreads();
    }
#pragma unroll
    for (int i = 0; i < 4; i++) {
        int row = m0 + ty * 4 + i;
        float4 v;
        v.x = acc[i][0]; v.y = acc[i][1]; v.z = acc[i][2]; v.w = acc[i][3];
        if (bias) {
            v.x += bias[n0 + tx * 4 + 0];
            v.y += bias[n0 + tx * 4 + 1];
            v.z += bias[n0 + tx * 4 + 2];
            v.w += bias[n0 + tx * 4 + 3];
        }
        *(float4*)(&C[(size_t)row * N + n0 + tx * 4]) = v;
    }
}

// ------------------------- rowwise LayerNorm over 768 ------------------------
__global__ void __launch_bounds__(256) ln_rows(float* __restrict__ xp,
                                               const float* __restrict__ gammas,
                                               const float* __restrict__ betas) {
    int r = blockIdx.x;
    float* row = xp + (size_t)r * H3;
    int t = threadIdx.x;
    float v0 = row[t], v1 = row[t + 256], v2 = row[t + 512];
    float s = v0 + v1 + v2;
    float q = v0 * v0 + v1 * v1 + v2 * v2;
    __shared__ float rs[8], rq[8];
    __shared__ float s_mu, s_rstd;
    float ws = warp_sum(s), wq = warp_sum(q);
    if ((t & 31) == 0) { rs[t >> 5] = ws; rq[t >> 5] = wq; }
    __syncthreads();
    if (t == 0) {
        float S = 0.f, Q = 0.f;
#pragma unroll
        for (int i = 0; i < 8; i++) { S += rs[i]; Q += rq[i]; }
        float mu  = S * (1.0f / 768.0f);
        float var = Q * (1.0f / 768.0f) - mu * mu;
        s_mu = mu;
        s_rstd = rsqrtf(var + 1e-5f);
    }
    __syncthreads();
    float mu = s_mu, rstd = s_rstd;
    row[t]       = gammas[t]       * (v0 - mu) * rstd + betas[t];
    row[t + 256] = gammas[t + 256] * (v1 - mu) * rstd + betas[t + 256];
    row[t + 512] = gammas[t + 512] * (v2 - mu) * rstd + betas[t + 512];
}

// --------------------- cluster-resident sequential scan -----------------------
// 16 clusters x 8 CTAs. Cluster c owns batches 4c..4c+3. CTA rank r holds rows
// 112r..112r+111 of [U^T; Ua1^T] in SMEM. One cluster barrier per timestep;
// matvec partials exchanged via L2 (double buffered); LN/gates/action head
// recomputed redundantly per CTA so h stays local.
__global__ void __cluster_dims__(CLUSTER_NCTAS, 1, 1) __launch_bounds__(SCAN_THREADS, 1)
scan2_kernel(int d,
             const float* __restrict__ bg,
             const float* __restrict__ gammas,
             const float* __restrict__ betas,
             const float* __restrict__ ba1,
             const float* __restrict__ Wa2,
             const float* __restrict__ ba2,
             float* __restrict__ out, int out_size) {
    extern __shared__ float sm[];
    float* Wsm   = sm;                         // 112*260 = 29120
    float* s_h   = Wsm  + ROWS_PER_CTA * W_PAD;// 4*260   = 1040
    float* s_hp  = s_h  + NBAT * W_PAD;        // 896*5   = 4480
    float* s_xp  = s_hp + 896 * 5;             // 4*768   = 3072
    float* s_xa  = s_xp + NBAT * H3;           // 4*128   = 512
    float* c_bg  = s_xa + NBAT * ADIM;         // 768
    float* c_g1  = c_bg + H3;                  // 768
    float* c_b1  = c_g1 + H3;                  // 768
    float* c_ba1 = c_b1 + H3;                  // 128
    float* c_wa2 = c_ba1 + ADIM;               // 256
    float* s_red = c_wa2 + 2 * ADIM;           // 64
    float* s_stat= s_red + 64;                 // 8
    unsigned char* s_mask = (unsigned char*)(s_stat + 8); // 4*512 bytes

    const int t    = threadIdx.x;
    const int rank = blockIdx.x & (CLUSTER_NCTAS - 1);
    const int clu  = blockIdx.x >> 3;
    const int b0   = clu * NBAT;

    // ---- load this CTA's weight slice (rows 112*rank .. +111), padded ----
    {
        const float4* src = (const float4*)(g_Ut2 + (size_t)(ROWS_PER_CTA * rank) * HDIM);
        for (int i = t; i < ROWS_PER_CTA * 64; i += SCAN_THREADS) {
            int row = i >> 6, c4 = i & 63;
            float4 v = src[(size_t)row * 64 + c4];
            float* dst = Wsm + row * W_PAD + c4 * 4;
            dst[0] = v.x; dst[1] = v.y; dst[2] = v.z; dst[3] = v.w;
        }
    }
    for (int i = t; i < H3; i += SCAN_THREADS) {
        c_bg[i] = bg[i];
        c_g1[i] = gammas[H3 + i];
        c_b1[i] = betas[H3 + i];
    }
    if (t < ADIM)     c_ba1[t] = ba1[t];
    if (t < 2 * ADIM) c_wa2[t] = Wa2[t];
    for (int i = t; i < NBAT * LSEQ; i += SCAN_THREADS)
        s_mask[i] = g_mask[(b0 + (i >> 9)) * LSEQ + (i & 511)];
    for (int i = t; i < NBAT * W_PAD; i += SCAN_THREADS) s_h[i] = 0.0f;
    __syncthreads();

    const bool write_full = (out_size >= 409600);
    const int wrow = t >> 2, wb = t & 3;                 // matvec mapping (t<448)
    float* hp_base = g_hp + (size_t)clu * (2 * 896 * NBAT);
    const float ba2_0 = ba2[0], ba2_1 = ba2[1];

    for (int l = 0; l < LSEQ; ++l) {
        const int par = l & 1;
        float* gout = hp_base + par * (896 * NBAT);

        // ---- phase A: matvec on SMEM weights (t<448) + xp/xa prefetch ----
        if (t < 448) {
            const float4* wp = (const float4*)(Wsm + wrow * W_PAD);
            const float4* hv = (const float4*)(s_h + wb * W_PAD);
            float a0 = 0.f, a1 = 0.f, a2 = 0.f, a3 = 0.f;
#pragma unroll
            for (int i = 0; i < 64; i += 4) {
                a0 += dp4(wp[i],     hv[i]);
                a1 += dp4(wp[i + 1], hv[i + 1]);
                a2 += dp4(wp[i + 2], hv[i + 2]);
                a3 += dp4(wp[i + 3], hv[i + 3]);
            }
            gout[rank * 448 + t] = (a0 + a1) + (a2 + a3);
        } else {
            int u = t - 448;
            const size_t grow = (size_t)l * BATCH + b0;
            for (int i = u; i < 768; i += 448) {           // 4x768 floats as float4
                int bb = i / 192, c4 = i % 192;
                float4 v = *(const float4*)(g_xp + (grow + bb) * H3 + c4 * 4);
                *(float4*)(s_xp + bb * H3 + c4 * 4) = v;
            }
            if (u < 128) {                                  // 4x128 floats as float4
                int bb = u >> 5, c4 = u & 31;
                float4 v = *(const float4*)(g_xa + (grow + bb) * ADIM + c4 * 4);
                *(float4*)(s_xa + bb * ADIM + c4 * 4) = v;
            }
        }

        // one cluster barrier per step: release matvec partials / acquire peers'
        asm volatile("barrier.cluster.arrive.aligned;" ::: "memory");
        asm volatile("barrier.cluster.wait.aligned;" ::: "memory");

        // ---- phase B: gather full hp (896x4), redundant LN/gates/action ----
        {
            float4 v = __ldcv(((const float4*)gout) + t);   // row t, 4 batches
            float* dst = s_hp + t * 5;
            dst[0] = v.x; dst[1] = v.y; dst[2] = v.z; dst[3] = v.w;
        }
        __syncthreads();

        // LN stats over rows 0..767 per batch (128 threads x 6 rows each)
        if (t < 512) {
            int bb = t >> 7, q = t & 127;
            float s = 0.f, qq = 0.f;
#pragma unroll
            for (int j = 0; j < 6; j++) {
                float v = s_hp[(q + 128 * j) * 5 + bb];
                s += v; qq += v * v;
            }
            s = warp_sum(s); qq = warp_sum(qq);
            if ((t & 31) == 0) { s_red[t >> 5] = s; s_red[16 + (t >> 5)] = qq; }
        }
        __syncthreads();
        if (t < 4) {
            float S = s_red[4 * t] + s_red[4 * t + 1] + s_red[4 * t + 2] + s_red[4 * t + 3];
            float Q = s_red[16 + 4 * t] + s_red[17 + 4 * t] + s_red[18 + 4 * t] + s_red[19 + 4 * t];
            float mu  = S * (1.0f / 768.0f);
            float var = Q * (1.0f / 768.0f) - mu * mu;
            s_stat[t]     = mu;
            s_stat[4 + t] = rsqrtf(var + 1e-5f);
        }
        __syncthreads();

        // gates: 1024 (batch,col) items
        for (int it = t; it < NBAT * HDIM; it += SCAN_THREADS) {
            int bb = it >> 8, col = it & 255;
            float mu = s_stat[bb], rs = s_stat[4 + bb];
            float hp0 = (s_hp[col * 5 + bb]         - mu) * rs * c_g1[col]       + c_b1[col];
            float hp1 = (s_hp[(col + 256) * 5 + bb] - mu) * rs * c_g1[col + 256] + c_b1[col + 256];
            float hp2 = (s_hp[(col + 512) * 5 + bb] - mu) * rs * c_g1[col + 512] + c_b1[col + 512];
            float r  = sigmoidf(s_xp[bb * H3 + col]       + hp0     + c_bg[col]);
            float z  = sigmoidf(s_xp[bb * H3 + col + 256] + hp1     + c_bg[col + 256]);
            float hh = tanhf   (s_xp[bb * H3 + col + 512] + r * hp2 + c_bg[col + 512]);
            float hold = s_h[bb * W_PAD + col];
            float hn = z * hold + (1.0f - z) * hh;
            float ho = s_mask[bb * LSEQ + l] ? hn : hold;
            s_h[bb * W_PAD + col] = ho;       // in-place: sole reader == this thread
            if (rank == bb) {
                g_hseq[((size_t)l * BATCH + b0 + bb) * HDIM + col] = ho;
                if (d == DEPTH - 1 && l == LSEQ - 1 && out_size >= BATCH * HDIM)
                    out[(b0 + bb) * HDIM + col] = ho;
            }
        }

        // action head: 512 (batch,k) items + per-batch reduction
        if (t < 512) {
            int bb = t >> 7, k = t & 127;
            float a = tanhf(s_xa[bb * ADIM + k] + s_hp[(H3 + k) * 5 + bb] + c_ba1[k]);
            float p0 = warp_sum(a * c_wa2[2 * k]);
            float p1 = warp_sum(a * c_wa2[2 * k + 1]);
            if ((t & 31) == 0) { s_red[32 + (t >> 5)] = p0; s_red[48 + (t >> 5)] = p1; }
        }
        __syncthreads();
        if (t < 4) {
            float l0 = s_red[32 + 4 * t] + s_red[33 + 4 * t] + s_red[34 + 4 * t] + s_red[35 + 4 * t] + ba2_0;
            float l1 = s_red[48 + 4 * t] + s_red[49 + 4 * t] + s_red[50 + 4 * t] + s_red[51 + 4 * t] + ba2_1;
            unsigned char mt  = s_mask[t * LSEQ + l];
            unsigned char act = ((l1 > l0) && mt) ? 1 : 0;
            s_mask[t * LSEQ + l] = act;                    // next-depth mask (local)
            if (rank == 4 + t) {
                g_mask[(b0 + t) * LSEQ + l] = act;
                if (write_full) {
                    float m = fmaxf(l0, l1);
                    float e0 = expf(l0 - m), e1 = expf(l1 - m);
                    float inv = 1.0f / (e0 + e1);
                    size_t ai = (size_t)BATCH * HDIM + ((size_t)((b0 + t) * DEPTH + d)) * LSEQ + l;
                    out[ai] = act ? 1.0f : 0.0f;
                    size_t pi = (size_t)BATCH * HDIM + (size_t)BATCH * DEPTH * LSEQ +
                                (((size_t)((b0 + t) * DEPTH + d)) * LSEQ + l) * 2;
                    out[pi]     = e0 * inv;
                    out[pi + 1] = e1 * inv;
                }
            }
        }
        __syncthreads();   // protect s_h / s_xp / s_mask before next step
    }
}

// --------------------------------- launcher ----------------------------------
extern "C" void kernel_launch(void* const* d_in, const int* in_sizes, int n_in,
                              void* d_out, int out_size) {
    const float* x     = (const float*)d_in[0];
    const unsigned char* mask = (const unsigned char*)d_in[1];
    const float* W_emb = (const float*)d_in[2];
    const float* b_emb = (const float*)d_in[3];
    const float* W     = (const float*)d_in[4];
    const float* U     = (const float*)d_in[5];
    const float* bgate = (const float*)d_in[6];
    const float* Wa1   = (const float*)d_in[7];
    const float* Ua1   = (const float*)d_in[8];
    const float* ba1   = (const float*)d_in[9];
    const float* Wa2   = (const float*)d_in[10];
    const float* ba2   = (const float*)d_in[11];
    const float* gammas = (const float*)d_in[12];
    const float* betas  = (const float*)d_in[13];
    float* out = (float*)d_out;

    float *hseq, *xp, *xa;
    cudaGetSymbolAddress((void**)&hseq, g_hseq);
    cudaGetSymbolAddress((void**)&xp, g_xp);
    cudaGetSymbolAddress((void**)&xa, g_xa);

    // dynamic SMEM for the scan kernel (idempotent; safe under graph capture)
    const int scan_smem = (ROWS_PER_CTA * W_PAD + NBAT * W_PAD + 896 * 5 + NBAT * H3 +
                           NBAT * ADIM + 3 * H3 + ADIM + 2 * ADIM + 64 + 8) * 4 + NBAT * LSEQ;
    static int attr_done = 0;
    if (!attr_done) {
        cudaFuncSetAttribute(scan2_kernel, cudaFuncAttributeMaxDynamicSharedMemorySize, scan_smem);
        attr_done = 1;
    }

    prep_weights<<<H3 + ADIM, HDIM>>>(U, Ua1);
    copy_mask<<<1, 1024>>>(mask);

    sgemm_kernel<true><<<dim3(HDIM / 64, NROWS / 64), 256>>>(x, W_emb, b_emb, hseq, HDIM);

    for (int d = 0; d < DEPTH; d++) {
        sgemm_kernel<false><<<dim3(H3 / 64, NROWS / 64), 256>>>(hseq, W, nullptr, xp, H3);
        sgemm_kernel<false><<<dim3(ADIM / 64, NROWS / 64), 256>>>(hseq, Wa1, nullptr, xa, ADIM);
        ln_rows<<<NROWS, 256>>>(xp, gammas, betas);
        scan2_kernel<<<NCLU * CLUSTER_NCTAS, SCAN_THREADS, scan_smem>>>(
            d, bgate, gammas, betas, ba1, Wa2, ba2, out, out_size);
    }
}